// round 8
// baseline (speedup 1.0000x reference)
#include <cuda_runtime.h>
#include <cuda_bf16.h>
#include <cstdint>
#include <math_constants.h>

#define BB 8
#define CC 256
#define NN 4096

// ---------------- device scratch (allocation-free rule) ----------------
__device__ __nv_bfloat16 g_Ft_hi[BB * NN * CC];   // feat^T [b][n][c]
__device__ __nv_bfloat16 g_Ft_lo[BB * NN * CC];
__device__ __nv_bfloat16 g_Zt_hi[BB * NN * CC];   // Z^T [b][m][c]
__device__ __nv_bfloat16 g_Zt_lo[BB * NN * CC];
__device__ __nv_bfloat16 g_Gk_hi[CC * CC];        // G [c][e]
__device__ __nv_bfloat16 g_Gk_lo[CC * CC];

// ---------------- SMEM layout ----------------
#define CH       16384                 // one 128x64 bf16 chunk, SW128 swizzled
#define OFF_A    0                     // 8 chunks (hi:0..3, lo:4..7) = 131072
#define OFF_B    131072                // 2 bufs x (hi+lo) = 2*32768
#define BUFSZ    32768
#define EP_DIAG  196608
#define SMEM_TOTAL 197632

__device__ __forceinline__ uint32_t smem_u32(const void* p) {
    uint32_t a;
    asm("{ .reg .u64 t; cvta.to.shared.u64 t, %1; cvt.u32.u64 %0, t; }" : "=r"(a) : "l"(p));
    return a;
}

#define CPA_COMMIT() asm volatile("cp.async.commit_group;" ::: "memory")
#define CPA_WAIT0()  asm volatile("cp.async.wait_group 0;" ::: "memory")

// 128 rows x 64 bf16 chunk (gmem row stride CC) -> SW128 swizzled smem, cp.async
__device__ __forceinline__ void cpa_chunk(uint32_t dst, const __nv_bfloat16* g, int tid) {
#pragma unroll
    for (int it = 0; it < 4; it++) {
        int u = tid + it * 256;
        int row = u >> 3, seg = u & 7;
        uint32_t bo = (uint32_t)(row * 128 + seg * 16);
        bo ^= ((bo >> 3) & 0x70);
        asm volatile("cp.async.cg.shared.global [%0], [%1], 16;"
                     :: "r"(dst + bo), "l"((const void*)(g + row * CC + seg * 8)) : "memory");
    }
}

// same, but synchronous LDG/STS (used once for the resident A tile)
__device__ __forceinline__ void copy_chunk(char* sm, uint32_t dst, const __nv_bfloat16* g, int tid) {
#pragma unroll
    for (int it = 0; it < 4; it++) {
        int u = tid + it * 256;
        int row = u >> 3, seg = u & 7;
        uint4 v = *(const uint4*)(g + row * CC + seg * 8);
        uint32_t bo = (uint32_t)(row * 128 + seg * 16);
        bo ^= ((bo >> 3) & 0x70);
        *(uint4*)(sm + dst + bo) = v;
    }
}

__device__ __forceinline__ void ldsm4(uint32_t addr, uint32_t r[4]) {
    asm volatile("ldmatrix.sync.aligned.m8n8.x4.shared.b16 {%0,%1,%2,%3}, [%4];"
                 : "=r"(r[0]), "=r"(r[1]), "=r"(r[2]), "=r"(r[3]) : "r"(addr));
}

__device__ __forceinline__ void mma16816(float d[4], const uint32_t a[4], uint32_t b0, uint32_t b1) {
    asm volatile("mma.sync.aligned.m16n8k16.row.col.f32.bf16.bf16.f32 "
                 "{%0,%1,%2,%3}, {%4,%5,%6,%7}, {%8,%9}, {%0,%1,%2,%3};"
                 : "+f"(d[0]), "+f"(d[1]), "+f"(d[2]), "+f"(d[3])
                 : "r"(a[0]), "r"(a[1]), "r"(a[2]), "r"(a[3]), "r"(b0), "r"(b1));
}

// -------- old 4x2 layout k-chunk (still used by k_z_mma) --------
__device__ __forceinline__ void mma_kchunk(uint32_t aH, uint32_t aL, uint32_t bH, uint32_t bL,
                                           uint32_t aro0, const uint32_t* bro,
                                           uint32_t lhi, uint32_t xorv, float acc[2][8][4]) {
#pragma unroll
    for (int ks = 0; ks < 4; ks++) {
        uint32_t cx = ((uint32_t)(ks * 32) + lhi) ^ xorv;
        uint32_t ah0[4], ah1[4], al0[4], al1[4];
        ldsm4(aH + aro0 + cx, ah0);
        ldsm4(aH + aro0 + 2048 + cx, ah1);
        ldsm4(aL + aro0 + cx, al0);
        ldsm4(aL + aro0 + 2048 + cx, al1);
#pragma unroll
        for (int g16 = 0; g16 < 4; g16++) {
            uint32_t bh[4], bl[4];
            ldsm4(bH + bro[g16] + cx, bh);
            ldsm4(bL + bro[g16] + cx, bl);
            const int g0 = 2 * g16, g1 = 2 * g16 + 1;
            mma16816(acc[0][g0], ah0, bh[0], bh[2]);
            mma16816(acc[1][g0], ah1, bh[0], bh[2]);
            mma16816(acc[0][g1], ah0, bh[1], bh[3]);
            mma16816(acc[1][g1], ah1, bh[1], bh[3]);
            mma16816(acc[0][g0], ah0, bl[0], bl[2]);
            mma16816(acc[1][g0], ah1, bl[0], bl[2]);
            mma16816(acc[0][g1], ah0, bl[1], bl[3]);
            mma16816(acc[1][g1], ah1, bl[1], bl[3]);
            mma16816(acc[0][g0], al0, bh[0], bh[2]);
            mma16816(acc[1][g0], al1, bh[0], bh[2]);
            mma16816(acc[0][g1], al0, bh[1], bh[3]);
            mma16816(acc[1][g1], al1, bh[1], bh[3]);
        }
    }
}

// -------- new row-stacked layout k-chunk: 16 rows x 128 cols per warp --------
__device__ __forceinline__ void mma_kchunk_rs(uint32_t aH, uint32_t aL, uint32_t bH, uint32_t bL,
                                              uint32_t aro0, const uint32_t* bro,
                                              uint32_t lhi, uint32_t xorv, float acc[16][4]) {
#pragma unroll
    for (int ks = 0; ks < 4; ks++) {
        uint32_t cx = ((uint32_t)(ks * 32) + lhi) ^ xorv;
        uint32_t ah[4], al[4];
        ldsm4(aH + aro0 + cx, ah);
        ldsm4(aL + aro0 + cx, al);
#pragma unroll
        for (int g16 = 0; g16 < 8; g16++) {
            uint32_t bh[4], bl[4];
            ldsm4(bH + bro[g16] + cx, bh);
            ldsm4(bL + bro[g16] + cx, bl);
            const int g0 = 2 * g16, g1 = 2 * g16 + 1;
            mma16816(acc[g0], ah, bh[0], bh[2]);
            mma16816(acc[g1], ah, bh[1], bh[3]);
            mma16816(acc[g0], ah, bl[0], bl[2]);
            mma16816(acc[g1], ah, bl[1], bl[3]);
            mma16816(acc[g0], al, bh[0], bh[2]);
            mma16816(acc[g1], al, bh[1], bh[3]);
        }
    }
}

// ---------------------------------------------------------------------------
// k_gt: G[c][e] = sum_d Wq[d][c]*Wk[d][e], bf16 hi/lo. grid 128, block 256.
// ---------------------------------------------------------------------------
__global__ void k_gt(const float* __restrict__ Wq, const float* __restrict__ Wk) {
    __shared__ float sq[2][CC];
    const int c0 = blockIdx.x * 2, e = threadIdx.x;
    sq[0][e] = Wq[e * CC + c0];
    sq[1][e] = Wq[e * CC + c0 + 1];
    __syncthreads();
    float a0 = 0.f, a1 = 0.f;
#pragma unroll 8
    for (int d = 0; d < CC; d++) {
        float wk = Wk[d * CC + e];
        a0 += sq[0][d] * wk;
        a1 += sq[1][d] * wk;
    }
    __nv_bfloat16 h0 = __float2bfloat16(a0), h1 = __float2bfloat16(a1);
    g_Gk_hi[c0 * CC + e] = h0;
    g_Gk_lo[c0 * CC + e] = __float2bfloat16(a0 - __bfloat162float(h0));
    g_Gk_hi[(c0 + 1) * CC + e] = h1;
    g_Gk_lo[(c0 + 1) * CC + e] = __float2bfloat16(a1 - __bfloat162float(h1));
}

// ---------------------------------------------------------------------------
// k_prep: Ft[b][n][c] = feat[b][c][n], bf16 hi/lo. grid (128,8,8), block (32,8)
// ---------------------------------------------------------------------------
__global__ void k_prep(const float* __restrict__ feat) {
    __shared__ float t[32][33];
    const int b = blockIdx.z, c0 = blockIdx.y * 32, n0 = blockIdx.x * 32;
    const int tx = threadIdx.x, ty = threadIdx.y;
    const float* F = feat + ((size_t)b * CC + c0) * NN + n0;
#pragma unroll
    for (int i = 0; i < 4; i++) t[ty + i * 8][tx] = F[(ty + i * 8) * NN + tx];
    __syncthreads();
#pragma unroll
    for (int i = 0; i < 4; i++) {
        int nr = ty + i * 8;
        float x = t[tx][nr];
        size_t o = ((size_t)b * NN + n0 + nr) * CC + c0 + tx;
        __nv_bfloat16 h = __float2bfloat16(x);
        g_Ft_hi[o] = h;
        g_Ft_lo[o] = __float2bfloat16(x - __bfloat162float(h));
    }
}

// ---------------------------------------------------------------------------
// k_z_mma: Zt[b][m][c] = sum_e Ft[m][e] * G[c][e].  grid (32, 8), 256 thr.
// ---------------------------------------------------------------------------
__global__ void __launch_bounds__(256, 1) k_z_mma() {
    extern __shared__ char sm[];
    const uint32_t smb = smem_u32(sm);
    const int tid = threadIdx.x, wid = tid >> 5, lane = tid & 31;
    const int m0 = blockIdx.x * 128, b = blockIdx.y;
    const int wr = wid & 3, wc = wid >> 2;
    const int l15 = lane & 15;
    const uint32_t lhi = (uint32_t)((lane >> 4) * 16);
    const uint32_t xorv = (uint32_t)((lane & 7) * 16);
    const uint32_t aro0 = (uint32_t)((wr * 32 + l15) * 128);
    uint32_t bro[4];
#pragma unroll
    for (int g16 = 0; g16 < 4; g16++) bro[g16] = (uint32_t)((wc * 64 + g16 * 16 + l15) * 128);

    cpa_chunk(smb + OFF_B, g_Gk_hi, tid);
    cpa_chunk(smb + OFF_B + CH, g_Gk_lo, tid);
    CPA_COMMIT();

    const __nv_bfloat16* Fh = g_Ft_hi + ((size_t)b * NN + m0) * CC;
    const __nv_bfloat16* Fl = g_Ft_lo + ((size_t)b * NN + m0) * CC;
#pragma unroll
    for (int cb = 0; cb < 8; cb++) {
        int p = cb >> 2, kc = cb & 3;
        copy_chunk(sm, OFF_A + cb * CH, (p ? Fl : Fh) + kc * 64, tid);
    }
    __syncthreads();

    for (int ch = 0; ch < 2; ch++) {
        float acc[2][8][4];
#pragma unroll
        for (int a = 0; a < 2; a++)
#pragma unroll
            for (int g = 0; g < 8; g++)
#pragma unroll
                for (int q = 0; q < 4; q++) acc[a][g][q] = 0.f;

#pragma unroll 1
        for (int kc = 0; kc < 4; kc++) {
            const int t = ch * 4 + kc;
            CPA_WAIT0();
            __syncthreads();
            if (t + 1 < 8) {
                int ch2 = (t + 1) >> 2, kc2 = (t + 1) & 3;
                uint32_t d = smb + OFF_B + ((t + 1) & 1) * BUFSZ;
                cpa_chunk(d, g_Gk_hi + (ch2 * 128) * CC + kc2 * 64, tid);
                cpa_chunk(d + CH, g_Gk_lo + (ch2 * 128) * CC + kc2 * 64, tid);
            }
            CPA_COMMIT();
            uint32_t bq = smb + OFF_B + (t & 1) * BUFSZ;
            mma_kchunk(smb + OFF_A + kc * CH, smb + OFF_A + (4 + kc) * CH,
                       bq, bq + CH, aro0, bro, lhi, xorv, acc);
        }

        const int g8 = lane >> 2, tig = lane & 3;
#pragma unroll
        for (int a = 0; a < 2; a++)
#pragma unroll
            for (int h = 0; h < 2; h++) {
                const int r = wr * 32 + a * 16 + h * 8 + g8;
                size_t rowoff = ((size_t)b * NN + m0 + r) * CC + ch * 128;
#pragma unroll
                for (int g = 0; g < 8; g++) {
                    const int cl = wc * 64 + g * 8 + tig * 2;
                    float x0 = acc[a][g][h * 2], x1 = acc[a][g][h * 2 + 1];
                    __nv_bfloat16 h0 = __float2bfloat16(x0), h1 = __float2bfloat16(x1);
                    __nv_bfloat16 l0 = __float2bfloat16(x0 - __bfloat162float(h0));
                    __nv_bfloat16 l1 = __float2bfloat16(x1 - __bfloat162float(h1));
                    *(__nv_bfloat162*)(g_Zt_hi + rowoff + cl) = __nv_bfloat162(h0, h1);
                    *(__nv_bfloat162*)(g_Zt_lo + rowoff + cl) = __nv_bfloat162(l0, l1);
                }
            }
    }
}

// ---------------------------------------------------------------------------
// k_attn_mma: streaming S = Ft·Zt^T; row-stacked warps (16 rows x 128 cols per
// warp) -> warp-private online softmax, zero barriers in the epilogue.
// grid (32, 8), 256 thr.
// ---------------------------------------------------------------------------
__global__ void __launch_bounds__(256, 1) k_attn_mma(const float* __restrict__ feat,
                                                     float* __restrict__ out) {
    extern __shared__ char sm[];
    const uint32_t smb = smem_u32(sm);
    const int tid = threadIdx.x, w = tid >> 5, lane = tid & 31;
    const int n0 = blockIdx.x * 128, b = blockIdx.y;
    const int l15 = lane & 15, g8 = lane >> 2, tig = lane & 3;
    const uint32_t lhi = (uint32_t)((lane >> 4) * 16);
    const uint32_t xorv = (uint32_t)((lane & 7) * 16);
    const uint32_t aro0 = (uint32_t)((w * 16 + l15) * 128);
    uint32_t bro[8];
#pragma unroll
    for (int g16 = 0; g16 < 8; g16++) bro[g16] = (uint32_t)((g16 * 16 + l15) * 128);

    float* diag = (float*)(sm + EP_DIAG);

    const __nv_bfloat16* Zh = g_Zt_hi + (size_t)b * NN * CC;
    const __nv_bfloat16* Zl = g_Zt_lo + (size_t)b * NN * CC;

    cpa_chunk(smb + OFF_B, Zh, tid);
    cpa_chunk(smb + OFF_B + CH, Zl, tid);
    CPA_COMMIT();

    const __nv_bfloat16* Fh = g_Ft_hi + ((size_t)b * NN + n0) * CC;
    const __nv_bfloat16* Fl = g_Ft_lo + ((size_t)b * NN + n0) * CC;
#pragma unroll
    for (int cb = 0; cb < 8; cb++) {
        int p = cb >> 2, kc = cb & 3;
        copy_chunk(sm, OFF_A + cb * CH, (p ? Fl : Fh) + kc * 64, tid);
    }
    __syncthreads();

    // per-lane softmax state for rows r0 = w*16+g8 and r1 = r0+8
    float runm0 = -CUDART_INF_F, runm1 = -CUDART_INF_F;
    float runl0 = 0.f, runl1 = 0.f;
    float dlog0 = 0.f, dlog1 = 0.f;
    const bool dlane = (tig == (g8 >> 1));   // lane holding the diagonal cols

#pragma unroll 1
    for (int mt = 0; mt < 32; mt++) {
        float acc[16][4];
#pragma unroll
        for (int g = 0; g < 16; g++)
#pragma unroll
            for (int q = 0; q < 4; q++) acc[g][q] = 0.f;

#pragma unroll 1
        for (int kc = 0; kc < 4; kc++) {
            const int t = mt * 4 + kc;
            CPA_WAIT0();
            __syncthreads();
            if (t + 1 < 128) {
                int mt2 = (t + 1) >> 2, kc2 = (t + 1) & 3;
                uint32_t d = smb + OFF_B + ((t + 1) & 1) * BUFSZ;
                cpa_chunk(d, Zh + (size_t)(mt2 * 128) * CC + kc2 * 64, tid);
                cpa_chunk(d + CH, Zl + (size_t)(mt2 * 128) * CC + kc2 * 64, tid);
            }
            CPA_COMMIT();
            uint32_t bq = smb + OFF_B + (t & 1) * BUFSZ;
            mma_kchunk_rs(smb + OFF_A + kc * CH, smb + OFF_A + (4 + kc) * CH,
                          bq, bq + CH, aro0, bro, lhi, xorv, acc);
        }

        // ---- warp-private online softmax (no barriers) ----
        float mx0 = -CUDART_INF_F, mx1 = -CUDART_INF_F;
#pragma unroll
        for (int g = 0; g < 16; g++) {
            mx0 = fmaxf(mx0, fmaxf(acc[g][0], acc[g][1]));
            mx1 = fmaxf(mx1, fmaxf(acc[g][2], acc[g][3]));
        }
        mx0 = fmaxf(mx0, __shfl_xor_sync(0xffffffffu, mx0, 1));
        mx0 = fmaxf(mx0, __shfl_xor_sync(0xffffffffu, mx0, 2));
        mx1 = fmaxf(mx1, __shfl_xor_sync(0xffffffffu, mx1, 1));
        mx1 = fmaxf(mx1, __shfl_xor_sync(0xffffffffu, mx1, 2));

        const float nm0 = fmaxf(runm0, mx0);
        const float nm1 = fmaxf(runm1, mx1);
        runl0 *= __expf(runm0 - nm0);
        runl1 *= __expf(runm1 - nm1);
        runm0 = nm0;
        runm1 = nm1;

        float s0 = 0.f, s1 = 0.f;
#pragma unroll
        for (int g = 0; g < 16; g++) {
            s0 += __expf(acc[g][0] - nm0) + __expf(acc[g][1] - nm0);
            s1 += __expf(acc[g][2] - nm1) + __expf(acc[g][3] - nm1);
        }
        s0 += __shfl_xor_sync(0xffffffffu, s0, 1);
        s0 += __shfl_xor_sync(0xffffffffu, s0, 2);
        s1 += __shfl_xor_sync(0xffffffffu, s1, 1);
        s1 += __shfl_xor_sync(0xffffffffu, s1, 2);
        runl0 += s0;
        runl1 += s1;

        if (mt == blockIdx.x && dlane) {
            // row r0 = w*16+g8 -> ngroup 2w, col-in-group g8; row r1 -> ngroup 2w+1
            dlog0 = acc[2 * w][g8 & 1];
            dlog1 = acc[2 * w + 1][2 + (g8 & 1)];
        }
    }

    if (dlane) {
        diag[w * 16 + g8]     = __expf(dlog0 - runm0) / runl0;
        diag[w * 16 + 8 + g8] = __expf(dlog1 - runm1) / runl1;
    }
    __syncthreads();

    const float* F = feat + (size_t)b * CC * NN;
    float* O = out + (size_t)b * CC * NN;
    for (int u = tid; u < CC * 32; u += 256) {
        int c = u >> 5, seg = u & 31;
        float4 f = *(const float4*)(F + (size_t)c * NN + n0 + seg * 4);
        float4 o;
        o.x = f.x * diag[seg * 4 + 0];
        o.y = f.y * diag[seg * 4 + 1];
        o.z = f.z * diag[seg * 4 + 2];
        o.w = f.w * diag[seg * 4 + 3];
        *(float4*)(O + (size_t)c * NN + n0 + seg * 4) = o;
    }
}

// ---------------------------------------------------------------------------
extern "C" void kernel_launch(void* const* d_in, const int* in_sizes, int n_in,
                              void* d_out, int out_size) {
    const float* feat = (const float*)d_in[0];  // [B,C,N]
    const float* Wq   = (const float*)d_in[1];  // [C,C]
    const float* Wk   = (const float*)d_in[2];  // [C,C]
    float* out = (float*)d_out;                 // [B,C,N]

    cudaFuncSetAttribute(k_z_mma, cudaFuncAttributeMaxDynamicSharedMemorySize, SMEM_TOTAL);
    cudaFuncSetAttribute(k_attn_mma, cudaFuncAttributeMaxDynamicSharedMemorySize, SMEM_TOTAL);

    k_gt<<<CC / 2, CC>>>(Wq, Wk);
    k_prep<<<dim3(NN / 32, CC / 32, BB), dim3(32, 8)>>>(feat);
    k_z_mma<<<dim3(NN / 128, BB), 256, SMEM_TOTAL>>>();
    k_attn_mma<<<dim3(NN / 128, BB), 256, SMEM_TOTAL>>>(feat, out);
}

// round 9
// speedup vs baseline: 2.1345x; 2.1345x over previous
#include <cuda_runtime.h>
#include <cuda_bf16.h>
#include <cstdint>
#include <math_constants.h>

#define BB 8
#define CC 256
#define NN 4096

// ---------------- device scratch (allocation-free rule) ----------------
__device__ __nv_bfloat16 g_Ft_hi[BB * NN * CC];   // feat^T [b][n][c]
__device__ __nv_bfloat16 g_Ft_lo[BB * NN * CC];
__device__ __nv_bfloat16 g_Zt_hi[BB * NN * CC];   // Z^T [b][m][c]
__device__ __nv_bfloat16 g_Zt_lo[BB * NN * CC];
__device__ __nv_bfloat16 g_Gk_hi[CC * CC];        // G [c][e]
__device__ __nv_bfloat16 g_Gk_lo[CC * CC];

// ---------------- SMEM layout ----------------
#define CH       16384                 // one 128x64 bf16 chunk, SW128 swizzled
#define OFF_A    0                     // 8 chunks (hi:0..3, lo:4..7) = 131072
#define OFF_B    131072                // 2 bufs x (hi+lo) = 2*32768
#define BUFSZ    32768
#define OFF_EPI  196608
#define EP_DLOG  (OFF_EPI + 0)         // 512 B
#define EP_MM    (OFF_EPI + 512)       // 2*512 B  (per-half row max)
#define EP_LL    (OFF_EPI + 1536)      // 2*512 B  (per-half row sumexp)
#define EP_DIAG  (OFF_EPI + 2560)      // 512 B
#define SMEM_TOTAL 199680

__device__ __forceinline__ uint32_t smem_u32(const void* p) {
    uint32_t a;
    asm("{ .reg .u64 t; cvta.to.shared.u64 t, %1; cvt.u32.u64 %0, t; }" : "=r"(a) : "l"(p));
    return a;
}

#define CPA_COMMIT() asm volatile("cp.async.commit_group;" ::: "memory")
#define CPA_WAIT0()  asm volatile("cp.async.wait_group 0;" ::: "memory")

// 128 rows x 64 bf16 chunk (gmem row stride CC) -> SW128 swizzled smem, cp.async
__device__ __forceinline__ void cpa_chunk(uint32_t dst, const __nv_bfloat16* g, int tid) {
#pragma unroll
    for (int it = 0; it < 4; it++) {
        int u = tid + it * 256;
        int row = u >> 3, seg = u & 7;
        uint32_t bo = (uint32_t)(row * 128 + seg * 16);
        bo ^= ((bo >> 3) & 0x70);
        asm volatile("cp.async.cg.shared.global [%0], [%1], 16;"
                     :: "r"(dst + bo), "l"((const void*)(g + row * CC + seg * 8)) : "memory");
    }
}

// same, but synchronous LDG/STS (used once for the resident A tile)
__device__ __forceinline__ void copy_chunk(char* sm, uint32_t dst, const __nv_bfloat16* g, int tid) {
#pragma unroll
    for (int it = 0; it < 4; it++) {
        int u = tid + it * 256;
        int row = u >> 3, seg = u & 7;
        uint4 v = *(const uint4*)(g + row * CC + seg * 8);
        uint32_t bo = (uint32_t)(row * 128 + seg * 16);
        bo ^= ((bo >> 3) & 0x70);
        *(uint4*)(sm + dst + bo) = v;
    }
}

__device__ __forceinline__ void ldsm4(uint32_t addr, uint32_t r[4]) {
    asm volatile("ldmatrix.sync.aligned.m8n8.x4.shared.b16 {%0,%1,%2,%3}, [%4];"
                 : "=r"(r[0]), "=r"(r[1]), "=r"(r[2]), "=r"(r[3]) : "r"(addr));
}

__device__ __forceinline__ void mma16816(float d[4], const uint32_t a[4], uint32_t b0, uint32_t b1) {
    asm volatile("mma.sync.aligned.m16n8k16.row.col.f32.bf16.bf16.f32 "
                 "{%0,%1,%2,%3}, {%4,%5,%6,%7}, {%8,%9}, {%0,%1,%2,%3};"
                 : "+f"(d[0]), "+f"(d[1]), "+f"(d[2]), "+f"(d[3])
                 : "r"(a[0]), "r"(a[1]), "r"(a[2]), "r"(a[3]), "r"(b0), "r"(b1));
}

// 4x2 warp layout k-chunk: 32 rows x 64 cols per warp (register-friendly)
__device__ __forceinline__ void mma_kchunk(uint32_t aH, uint32_t aL, uint32_t bH, uint32_t bL,
                                           uint32_t aro0, const uint32_t* bro,
                                           uint32_t lhi, uint32_t xorv, float acc[2][8][4]) {
#pragma unroll
    for (int ks = 0; ks < 4; ks++) {
        uint32_t cx = ((uint32_t)(ks * 32) + lhi) ^ xorv;
        uint32_t ah0[4], ah1[4], al0[4], al1[4];
        ldsm4(aH + aro0 + cx, ah0);
        ldsm4(aH + aro0 + 2048 + cx, ah1);
        ldsm4(aL + aro0 + cx, al0);
        ldsm4(aL + aro0 + 2048 + cx, al1);
#pragma unroll
        for (int g16 = 0; g16 < 4; g16++) {
            uint32_t bh[4], bl[4];
            ldsm4(bH + bro[g16] + cx, bh);
            ldsm4(bL + bro[g16] + cx, bl);
            const int g0 = 2 * g16, g1 = 2 * g16 + 1;
            mma16816(acc[0][g0], ah0, bh[0], bh[2]);
            mma16816(acc[1][g0], ah1, bh[0], bh[2]);
            mma16816(acc[0][g1], ah0, bh[1], bh[3]);
            mma16816(acc[1][g1], ah1, bh[1], bh[3]);
            mma16816(acc[0][g0], ah0, bl[0], bl[2]);
            mma16816(acc[1][g0], ah1, bl[0], bl[2]);
            mma16816(acc[0][g1], ah0, bl[1], bl[3]);
            mma16816(acc[1][g1], ah1, bl[1], bl[3]);
            mma16816(acc[0][g0], al0, bh[0], bh[2]);
            mma16816(acc[1][g0], al1, bh[0], bh[2]);
            mma16816(acc[0][g1], al0, bh[1], bh[3]);
            mma16816(acc[1][g1], al1, bh[1], bh[3]);
        }
    }
}

// ---------------------------------------------------------------------------
// k_gt: G[c][e] = sum_d Wq[d][c]*Wk[d][e], bf16 hi/lo. grid 128, block 256.
// ---------------------------------------------------------------------------
__global__ void k_gt(const float* __restrict__ Wq, const float* __restrict__ Wk) {
    __shared__ float sq[2][CC];
    const int c0 = blockIdx.x * 2, e = threadIdx.x;
    sq[0][e] = Wq[e * CC + c0];
    sq[1][e] = Wq[e * CC + c0 + 1];
    __syncthreads();
    float a0 = 0.f, a1 = 0.f;
#pragma unroll 8
    for (int d = 0; d < CC; d++) {
        float wk = Wk[d * CC + e];
        a0 += sq[0][d] * wk;
        a1 += sq[1][d] * wk;
    }
    __nv_bfloat16 h0 = __float2bfloat16(a0), h1 = __float2bfloat16(a1);
    g_Gk_hi[c0 * CC + e] = h0;
    g_Gk_lo[c0 * CC + e] = __float2bfloat16(a0 - __bfloat162float(h0));
    g_Gk_hi[(c0 + 1) * CC + e] = h1;
    g_Gk_lo[(c0 + 1) * CC + e] = __float2bfloat16(a1 - __bfloat162float(h1));
}

// ---------------------------------------------------------------------------
// k_prep: Ft[b][n][c] = feat[b][c][n], bf16 hi/lo. grid (128,8,8), block (32,8)
// ---------------------------------------------------------------------------
__global__ void k_prep(const float* __restrict__ feat) {
    __shared__ float t[32][33];
    const int b = blockIdx.z, c0 = blockIdx.y * 32, n0 = blockIdx.x * 32;
    const int tx = threadIdx.x, ty = threadIdx.y;
    const float* F = feat + ((size_t)b * CC + c0) * NN + n0;
#pragma unroll
    for (int i = 0; i < 4; i++) t[ty + i * 8][tx] = F[(ty + i * 8) * NN + tx];
    __syncthreads();
#pragma unroll
    for (int i = 0; i < 4; i++) {
        int nr = ty + i * 8;
        float x = t[tx][nr];
        size_t o = ((size_t)b * NN + n0 + nr) * CC + c0 + tx;
        __nv_bfloat16 h = __float2bfloat16(x);
        g_Ft_hi[o] = h;
        g_Ft_lo[o] = __float2bfloat16(x - __bfloat162float(h));
    }
}

// ---------------------------------------------------------------------------
// k_z_mma: Zt[b][m][c] = sum_e Ft[m][e] * G[c][e].  grid (32, 8), 256 thr.
// ---------------------------------------------------------------------------
__global__ void __launch_bounds__(256, 1) k_z_mma() {
    extern __shared__ char sm[];
    const uint32_t smb = smem_u32(sm);
    const int tid = threadIdx.x, wid = tid >> 5, lane = tid & 31;
    const int m0 = blockIdx.x * 128, b = blockIdx.y;
    const int wr = wid & 3, wc = wid >> 2;
    const int l15 = lane & 15;
    const uint32_t lhi = (uint32_t)((lane >> 4) * 16);
    const uint32_t xorv = (uint32_t)((lane & 7) * 16);
    const uint32_t aro0 = (uint32_t)((wr * 32 + l15) * 128);
    uint32_t bro[4];
#pragma unroll
    for (int g16 = 0; g16 < 4; g16++) bro[g16] = (uint32_t)((wc * 64 + g16 * 16 + l15) * 128);

    cpa_chunk(smb + OFF_B, g_Gk_hi, tid);
    cpa_chunk(smb + OFF_B + CH, g_Gk_lo, tid);
    CPA_COMMIT();

    const __nv_bfloat16* Fh = g_Ft_hi + ((size_t)b * NN + m0) * CC;
    const __nv_bfloat16* Fl = g_Ft_lo + ((size_t)b * NN + m0) * CC;
#pragma unroll
    for (int cb = 0; cb < 8; cb++) {
        int p = cb >> 2, kc = cb & 3;
        copy_chunk(sm, OFF_A + cb * CH, (p ? Fl : Fh) + kc * 64, tid);
    }
    __syncthreads();

    for (int ch = 0; ch < 2; ch++) {
        float acc[2][8][4];
#pragma unroll
        for (int a = 0; a < 2; a++)
#pragma unroll
            for (int g = 0; g < 8; g++)
#pragma unroll
                for (int q = 0; q < 4; q++) acc[a][g][q] = 0.f;

#pragma unroll 1
        for (int kc = 0; kc < 4; kc++) {
            const int t = ch * 4 + kc;
            CPA_WAIT0();
            __syncthreads();
            if (t + 1 < 8) {
                int ch2 = (t + 1) >> 2, kc2 = (t + 1) & 3;
                uint32_t d = smb + OFF_B + ((t + 1) & 1) * BUFSZ;
                cpa_chunk(d, g_Gk_hi + (ch2 * 128) * CC + kc2 * 64, tid);
                cpa_chunk(d + CH, g_Gk_lo + (ch2 * 128) * CC + kc2 * 64, tid);
            }
            CPA_COMMIT();
            uint32_t bq = smb + OFF_B + (t & 1) * BUFSZ;
            mma_kchunk(smb + OFF_A + kc * CH, smb + OFF_A + (4 + kc) * CH,
                       bq, bq + CH, aro0, bro, lhi, xorv, acc);
        }

        const int g8 = lane >> 2, tig = lane & 3;
#pragma unroll
        for (int a = 0; a < 2; a++)
#pragma unroll
            for (int h = 0; h < 2; h++) {
                const int r = wr * 32 + a * 16 + h * 8 + g8;
                size_t rowoff = ((size_t)b * NN + m0 + r) * CC + ch * 128;
#pragma unroll
                for (int g = 0; g < 8; g++) {
                    const int cl = wc * 64 + g * 8 + tig * 2;
                    float x0 = acc[a][g][h * 2], x1 = acc[a][g][h * 2 + 1];
                    __nv_bfloat16 h0 = __float2bfloat16(x0), h1 = __float2bfloat16(x1);
                    __nv_bfloat16 l0 = __float2bfloat16(x0 - __bfloat162float(h0));
                    __nv_bfloat16 l1 = __float2bfloat16(x1 - __bfloat162float(h1));
                    *(__nv_bfloat162*)(g_Zt_hi + rowoff + cl) = __nv_bfloat162(h0, h1);
                    *(__nv_bfloat162*)(g_Zt_lo + rowoff + cl) = __nv_bfloat162(l0, l1);
                }
            }
    }
}

// ---------------------------------------------------------------------------
// k_attn_mma: streaming S = Ft·Zt^T with the 4x2 warp layout; each warp keeps
// a PRIVATE online softmax over its 64-col slice; the two half-row partials
// merge ONCE after the m-loop. Zero per-tile barriers in the epilogue.
// grid (32, 8), 256 thr.
// ---------------------------------------------------------------------------
__global__ void __launch_bounds__(256, 1) k_attn_mma(const float* __restrict__ feat,
                                                     float* __restrict__ out) {
    extern __shared__ char sm[];
    const uint32_t smb = smem_u32(sm);
    const int tid = threadIdx.x, wid = tid >> 5, lane = tid & 31;
    const int n0 = blockIdx.x * 128, b = blockIdx.y;
    const int wr = wid & 3, wc = wid >> 2;
    const int l15 = lane & 15, g8 = lane >> 2, tig = lane & 3;
    const uint32_t lhi = (uint32_t)((lane >> 4) * 16);
    const uint32_t xorv = (uint32_t)((lane & 7) * 16);
    const uint32_t aro0 = (uint32_t)((wr * 32 + l15) * 128);
    uint32_t bro[4];
#pragma unroll
    for (int g16 = 0; g16 < 4; g16++) bro[g16] = (uint32_t)((wc * 64 + g16 * 16 + l15) * 128);

    float* dlog = (float*)(sm + EP_DLOG);
    float* mmH  = (float*)(sm + EP_MM);    // [2][128]
    float* llH  = (float*)(sm + EP_LL);    // [2][128]
    float* diag = (float*)(sm + EP_DIAG);

    const __nv_bfloat16* Zh = g_Zt_hi + (size_t)b * NN * CC;
    const __nv_bfloat16* Zl = g_Zt_lo + (size_t)b * NN * CC;

    cpa_chunk(smb + OFF_B, Zh, tid);
    cpa_chunk(smb + OFF_B + CH, Zl, tid);
    CPA_COMMIT();

    const __nv_bfloat16* Fh = g_Ft_hi + ((size_t)b * NN + n0) * CC;
    const __nv_bfloat16* Fl = g_Ft_lo + ((size_t)b * NN + n0) * CC;
#pragma unroll
    for (int cb = 0; cb < 8; cb++) {
        int p = cb >> 2, kc = cb & 3;
        copy_chunk(sm, OFF_A + cb * CH, (p ? Fl : Fh) + kc * 64, tid);
    }
    __syncthreads();

    // warp-private online softmax state over this warp's 64-col slice.
    // 4 rows per lane: idx = a*2+h -> row wr*32 + a*16 + h*8 + g8
    float runm[4] = {-CUDART_INF_F, -CUDART_INF_F, -CUDART_INF_F, -CUDART_INF_F};
    float runl[4] = {0.f, 0.f, 0.f, 0.f};

#pragma unroll 1
    for (int mt = 0; mt < 32; mt++) {
        float acc[2][8][4];
#pragma unroll
        for (int a = 0; a < 2; a++)
#pragma unroll
            for (int g = 0; g < 8; g++)
#pragma unroll
                for (int q = 0; q < 4; q++) acc[a][g][q] = 0.f;

#pragma unroll 1
        for (int kc = 0; kc < 4; kc++) {
            const int t = mt * 4 + kc;
            CPA_WAIT0();
            __syncthreads();
            if (t + 1 < 128) {
                int mt2 = (t + 1) >> 2, kc2 = (t + 1) & 3;
                uint32_t d = smb + OFF_B + ((t + 1) & 1) * BUFSZ;
                cpa_chunk(d, Zh + (size_t)(mt2 * 128) * CC + kc2 * 64, tid);
                cpa_chunk(d + CH, Zl + (size_t)(mt2 * 128) * CC + kc2 * 64, tid);
            }
            CPA_COMMIT();
            uint32_t bq = smb + OFF_B + (t & 1) * BUFSZ;
            mma_kchunk(smb + OFF_A + kc * CH, smb + OFF_A + (4 + kc) * CH,
                       bq, bq + CH, aro0, bro, lhi, xorv, acc);
        }

        // ---- warp-private partial softmax over the 64-col slice (no barriers) ----
#pragma unroll
        for (int a = 0; a < 2; a++)
#pragma unroll
            for (int h = 0; h < 2; h++) {
                const int idx = a * 2 + h;
                float mx = -CUDART_INF_F;
#pragma unroll
                for (int g = 0; g < 8; g++)
                    mx = fmaxf(mx, fmaxf(acc[a][g][h * 2], acc[a][g][h * 2 + 1]));
                mx = fmaxf(mx, __shfl_xor_sync(0xffffffffu, mx, 1));
                mx = fmaxf(mx, __shfl_xor_sync(0xffffffffu, mx, 2));
                const float nm = fmaxf(runm[idx], mx);
                float s = 0.f;
#pragma unroll
                for (int g = 0; g < 8; g++) {
                    s += __expf(acc[a][g][h * 2] - nm);
                    s += __expf(acc[a][g][h * 2 + 1] - nm);
                }
                s += __shfl_xor_sync(0xffffffffu, s, 1);
                s += __shfl_xor_sync(0xffffffffu, s, 2);
                runl[idx] = runl[idx] * __expf(runm[idx] - nm) + s;
                runm[idx] = nm;
            }

        if (mt == blockIdx.x) {  // diagonal tile: capture raw logit l_nn
#pragma unroll
            for (int a = 0; a < 2; a++)
#pragma unroll
                for (int h = 0; h < 2; h++) {
                    const int rl = wr * 32 + a * 16 + h * 8 + g8;
#pragma unroll
                    for (int g = 0; g < 8; g++)
#pragma unroll
                        for (int j = 0; j < 2; j++) {
                            const int cl = wc * 64 + g * 8 + tig * 2 + j;
                            if (cl == rl) dlog[rl] = acc[a][g][h * 2 + j];
                        }
                }
        }
    }

    // ---- one-time merge of the two half-row partials ----
    if (tig == 0) {
#pragma unroll
        for (int a = 0; a < 2; a++)
#pragma unroll
            for (int h = 0; h < 2; h++) {
                const int idx = a * 2 + h;
                const int rl = wr * 32 + a * 16 + h * 8 + g8;
                mmH[wc * 128 + rl] = runm[idx];
                llH[wc * 128 + rl] = runl[idx];
            }
    }
    __syncthreads();
    if (tid < 128) {
        float m0 = mmH[tid], m1 = mmH[128 + tid];
        float m = fmaxf(m0, m1);
        float l = llH[tid] * __expf(m0 - m) + llH[128 + tid] * __expf(m1 - m);
        diag[tid] = __expf(dlog[tid] - m) / l;
    }
    __syncthreads();

    const float* F = feat + (size_t)b * CC * NN;
    float* O = out + (size_t)b * CC * NN;
    for (int u = tid; u < CC * 32; u += 256) {
        int c = u >> 5, seg = u & 31;
        float4 f = *(const float4*)(F + (size_t)c * NN + n0 + seg * 4);
        float4 o;
        o.x = f.x * diag[seg * 4 + 0];
        o.y = f.y * diag[seg * 4 + 1];
        o.z = f.z * diag[seg * 4 + 2];
        o.w = f.w * diag[seg * 4 + 3];
        *(float4*)(O + (size_t)c * NN + n0 + seg * 4) = o;
    }
}

// ---------------------------------------------------------------------------
extern "C" void kernel_launch(void* const* d_in, const int* in_sizes, int n_in,
                              void* d_out, int out_size) {
    const float* feat = (const float*)d_in[0];  // [B,C,N]
    const float* Wq   = (const float*)d_in[1];  // [C,C]
    const float* Wk   = (const float*)d_in[2];  // [C,C]
    float* out = (float*)d_out;                 // [B,C,N]

    cudaFuncSetAttribute(k_z_mma, cudaFuncAttributeMaxDynamicSharedMemorySize, SMEM_TOTAL);
    cudaFuncSetAttribute(k_attn_mma, cudaFuncAttributeMaxDynamicSharedMemorySize, SMEM_TOTAL);

    k_gt<<<CC / 2, CC>>>(Wq, Wk);
    k_prep<<<dim3(NN / 32, CC / 32, BB), dim3(32, 8)>>>(feat);
    k_z_mma<<<dim3(NN / 128, BB), 256, SMEM_TOTAL>>>();
    k_attn_mma<<<dim3(NN / 128, BB), 256, SMEM_TOTAL>>>(feat, out);
}

// round 11
// speedup vs baseline: 2.1414x; 1.0032x over previous
#include <cuda_runtime.h>
#include <cuda_bf16.h>
#include <cstdint>
#include <math_constants.h>

#define BB 8
#define CC 256
#define NN 4096

// ---------------- device scratch (allocation-free rule) ----------------
__device__ __nv_bfloat16 g_Ft_hi[BB * NN * CC];   // feat^T [b][n][c]
__device__ __nv_bfloat16 g_Ft_lo[BB * NN * CC];
__device__ __nv_bfloat16 g_Zt_hi[BB * NN * CC];   // Z^T [b][m][c]
__device__ __nv_bfloat16 g_Zt_lo[BB * NN * CC];
__device__ __nv_bfloat16 g_Gk_hi[CC * CC];        // G [c][e]
__device__ __nv_bfloat16 g_Gk_lo[CC * CC];

// ---------------- SMEM layout ----------------
#define CH       16384                 // one 128x64 bf16 chunk, SW128 swizzled
#define OFF_A    0                     // 8 chunks (hi:0..3, lo:4..7) = 131072
#define OFF_B    131072                // 2 bufs x (hi+lo) = 2*32768
#define BUFSZ    32768
#define OFF_EPI  196608
#define EP_DLOG  (OFF_EPI + 0)         // 512 B
#define EP_MM    (OFF_EPI + 512)       // 2*512 B  (per-half row max)
#define EP_LL    (OFF_EPI + 1536)      // 2*512 B  (per-half row sumexp)
#define EP_DIAG  (OFF_EPI + 2560)      // 512 B
#define SMEM_TOTAL 199680

__device__ __forceinline__ uint32_t smem_u32(const void* p) {
    uint32_t a;
    asm("{ .reg .u64 t; cvta.to.shared.u64 t, %1; cvt.u32.u64 %0, t; }" : "=r"(a) : "l"(p));
    return a;
}

#define CPA_COMMIT() asm volatile("cp.async.commit_group;" ::: "memory")
#define CPA_WAIT0()  asm volatile("cp.async.wait_group 0;" ::: "memory")

// 128 rows x 64 bf16 chunk (gmem row stride CC) -> SW128 swizzled smem, cp.async
// 256-thread version (k_z_mma)
__device__ __forceinline__ void cpa_chunk(uint32_t dst, const __nv_bfloat16* g, int tid) {
#pragma unroll
    for (int it = 0; it < 4; it++) {
        int u = tid + it * 256;
        int row = u >> 3, seg = u & 7;
        uint32_t bo = (uint32_t)(row * 128 + seg * 16);
        bo ^= ((bo >> 3) & 0x70);
        asm volatile("cp.async.cg.shared.global [%0], [%1], 16;"
                     :: "r"(dst + bo), "l"((const void*)(g + row * CC + seg * 8)) : "memory");
    }
}
// 512-thread version (k_attn_mma)
__device__ __forceinline__ void cpa_chunk512(uint32_t dst, const __nv_bfloat16* g, int tid) {
#pragma unroll
    for (int it = 0; it < 2; it++) {
        int u = tid + it * 512;
        int row = u >> 3, seg = u & 7;
        uint32_t bo = (uint32_t)(row * 128 + seg * 16);
        bo ^= ((bo >> 3) & 0x70);
        asm volatile("cp.async.cg.shared.global [%0], [%1], 16;"
                     :: "r"(dst + bo), "l"((const void*)(g + row * CC + seg * 8)) : "memory");
    }
}

// synchronous LDG/STS copies (resident A tile)
__device__ __forceinline__ void copy_chunk(char* sm, uint32_t dst, const __nv_bfloat16* g, int tid) {
#pragma unroll
    for (int it = 0; it < 4; it++) {
        int u = tid + it * 256;
        int row = u >> 3, seg = u & 7;
        uint4 v = *(const uint4*)(g + row * CC + seg * 8);
        uint32_t bo = (uint32_t)(row * 128 + seg * 16);
        bo ^= ((bo >> 3) & 0x70);
        *(uint4*)(sm + dst + bo) = v;
    }
}
__device__ __forceinline__ void copy_chunk512(char* sm, uint32_t dst, const __nv_bfloat16* g, int tid) {
#pragma unroll
    for (int it = 0; it < 2; it++) {
        int u = tid + it * 512;
        int row = u >> 3, seg = u & 7;
        uint4 v = *(const uint4*)(g + row * CC + seg * 8);
        uint32_t bo = (uint32_t)(row * 128 + seg * 16);
        bo ^= ((bo >> 3) & 0x70);
        *(uint4*)(sm + dst + bo) = v;
    }
}

__device__ __forceinline__ void ldsm4(uint32_t addr, uint32_t r[4]) {
    asm volatile("ldmatrix.sync.aligned.m8n8.x4.shared.b16 {%0,%1,%2,%3}, [%4];"
                 : "=r"(r[0]), "=r"(r[1]), "=r"(r[2]), "=r"(r[3]) : "r"(addr));
}

__device__ __forceinline__ void mma16816(float d[4], const uint32_t a[4], uint32_t b0, uint32_t b1) {
    asm volatile("mma.sync.aligned.m16n8k16.row.col.f32.bf16.bf16.f32 "
                 "{%0,%1,%2,%3}, {%4,%5,%6,%7}, {%8,%9}, {%0,%1,%2,%3};"
                 : "+f"(d[0]), "+f"(d[1]), "+f"(d[2]), "+f"(d[3])
                 : "r"(a[0]), "r"(a[1]), "r"(a[2]), "r"(a[3]), "r"(b0), "r"(b1));
}

// 4x2 warp layout k-chunk: 32 rows x 64 cols per warp (k_z_mma, 8 warps)
__device__ __forceinline__ void mma_kchunk(uint32_t aH, uint32_t aL, uint32_t bH, uint32_t bL,
                                           uint32_t aro0, const uint32_t* bro,
                                           uint32_t lhi, uint32_t xorv, float acc[2][8][4]) {
#pragma unroll
    for (int ks = 0; ks < 4; ks++) {
        uint32_t cx = ((uint32_t)(ks * 32) + lhi) ^ xorv;
        uint32_t ah0[4], ah1[4], al0[4], al1[4];
        ldsm4(aH + aro0 + cx, ah0);
        ldsm4(aH + aro0 + 2048 + cx, ah1);
        ldsm4(aL + aro0 + cx, al0);
        ldsm4(aL + aro0 + 2048 + cx, al1);
#pragma unroll
        for (int g16 = 0; g16 < 4; g16++) {
            uint32_t bh[4], bl[4];
            ldsm4(bH + bro[g16] + cx, bh);
            ldsm4(bL + bro[g16] + cx, bl);
            const int g0 = 2 * g16, g1 = 2 * g16 + 1;
            mma16816(acc[0][g0], ah0, bh[0], bh[2]);
            mma16816(acc[1][g0], ah1, bh[0], bh[2]);
            mma16816(acc[0][g1], ah0, bh[1], bh[3]);
            mma16816(acc[1][g1], ah1, bh[1], bh[3]);
            mma16816(acc[0][g0], ah0, bl[0], bl[2]);
            mma16816(acc[1][g0], ah1, bl[0], bl[2]);
            mma16816(acc[0][g1], ah0, bl[1], bl[3]);
            mma16816(acc[1][g1], ah1, bl[1], bl[3]);
            mma16816(acc[0][g0], al0, bh[0], bh[2]);
            mma16816(acc[1][g0], al1, bh[0], bh[2]);
            mma16816(acc[0][g1], al0, bh[1], bh[3]);
            mma16816(acc[1][g1], al1, bh[1], bh[3]);
        }
    }
}

// 8x2 warp layout k-chunk: 16 rows x 64 cols per warp (k_attn_mma, 16 warps)
__device__ __forceinline__ void mma_kchunk_82(uint32_t aH, uint32_t aL, uint32_t bH, uint32_t bL,
                                              uint32_t aro0, const uint32_t* bro,
                                              uint32_t lhi, uint32_t xorv, float acc[8][4]) {
#pragma unroll
    for (int ks = 0; ks < 4; ks++) {
        uint32_t cx = ((uint32_t)(ks * 32) + lhi) ^ xorv;
        uint32_t ah[4], al[4];
        ldsm4(aH + aro0 + cx, ah);
        ldsm4(aL + aro0 + cx, al);
#pragma unroll
        for (int g16 = 0; g16 < 4; g16++) {
            uint32_t bh[4], bl[4];
            ldsm4(bH + bro[g16] + cx, bh);
            ldsm4(bL + bro[g16] + cx, bl);
            const int g0 = 2 * g16, g1 = 2 * g16 + 1;
            mma16816(acc[g0], ah, bh[0], bh[2]);
            mma16816(acc[g1], ah, bh[1], bh[3]);
            mma16816(acc[g0], ah, bl[0], bl[2]);
            mma16816(acc[g1], ah, bl[1], bl[3]);
            mma16816(acc[g0], al, bh[0], bh[2]);
            mma16816(acc[g1], al, bh[1], bh[3]);
        }
    }
}

// ---------------------------------------------------------------------------
// k_gt: G[c][e] = sum_d Wq[d][c]*Wk[d][e], bf16 hi/lo. grid 128, block 256.
// ---------------------------------------------------------------------------
__global__ void k_gt(const float* __restrict__ Wq, const float* __restrict__ Wk) {
    __shared__ float sq[2][CC];
    const int c0 = blockIdx.x * 2, e = threadIdx.x;
    sq[0][e] = Wq[e * CC + c0];
    sq[1][e] = Wq[e * CC + c0 + 1];
    __syncthreads();
    float a0 = 0.f, a1 = 0.f;
#pragma unroll 8
    for (int d = 0; d < CC; d++) {
        float wk = Wk[d * CC + e];
        a0 += sq[0][d] * wk;
        a1 += sq[1][d] * wk;
    }
    __nv_bfloat16 h0 = __float2bfloat16(a0), h1 = __float2bfloat16(a1);
    g_Gk_hi[c0 * CC + e] = h0;
    g_Gk_lo[c0 * CC + e] = __float2bfloat16(a0 - __bfloat162float(h0));
    g_Gk_hi[(c0 + 1) * CC + e] = h1;
    g_Gk_lo[(c0 + 1) * CC + e] = __float2bfloat16(a1 - __bfloat162float(h1));
}

// ---------------------------------------------------------------------------
// k_prep: Ft[b][n][c] = feat[b][c][n], bf16 hi/lo. grid (128,8,8), block (32,8)
// ---------------------------------------------------------------------------
__global__ void k_prep(const float* __restrict__ feat) {
    __shared__ float t[32][33];
    const int b = blockIdx.z, c0 = blockIdx.y * 32, n0 = blockIdx.x * 32;
    const int tx = threadIdx.x, ty = threadIdx.y;
    const float* F = feat + ((size_t)b * CC + c0) * NN + n0;
#pragma unroll
    for (int i = 0; i < 4; i++) t[ty + i * 8][tx] = F[(ty + i * 8) * NN + tx];
    __syncthreads();
#pragma unroll
    for (int i = 0; i < 4; i++) {
        int nr = ty + i * 8;
        float x = t[tx][nr];
        size_t o = ((size_t)b * NN + n0 + nr) * CC + c0 + tx;
        __nv_bfloat16 h = __float2bfloat16(x);
        g_Ft_hi[o] = h;
        g_Ft_lo[o] = __float2bfloat16(x - __bfloat162float(h));
    }
}

// ---------------------------------------------------------------------------
// k_z_mma: Zt[b][m][c] = sum_e Ft[m][e] * G[c][e].  grid (32, 8), 256 thr.
// ---------------------------------------------------------------------------
__global__ void __launch_bounds__(256, 1) k_z_mma() {
    extern __shared__ char sm[];
    const uint32_t smb = smem_u32(sm);
    const int tid = threadIdx.x, wid = tid >> 5, lane = tid & 31;
    const int m0 = blockIdx.x * 128, b = blockIdx.y;
    const int wr = wid & 3, wc = wid >> 2;
    const int l15 = lane & 15;
    const uint32_t lhi = (uint32_t)((lane >> 4) * 16);
    const uint32_t xorv = (uint32_t)((lane & 7) * 16);
    const uint32_t aro0 = (uint32_t)((wr * 32 + l15) * 128);
    uint32_t bro[4];
#pragma unroll
    for (int g16 = 0; g16 < 4; g16++) bro[g16] = (uint32_t)((wc * 64 + g16 * 16 + l15) * 128);

    cpa_chunk(smb + OFF_B, g_Gk_hi, tid);
    cpa_chunk(smb + OFF_B + CH, g_Gk_lo, tid);
    CPA_COMMIT();

    const __nv_bfloat16* Fh = g_Ft_hi + ((size_t)b * NN + m0) * CC;
    const __nv_bfloat16* Fl = g_Ft_lo + ((size_t)b * NN + m0) * CC;
#pragma unroll
    for (int cb = 0; cb < 8; cb++) {
        int p = cb >> 2, kc = cb & 3;
        copy_chunk(sm, OFF_A + cb * CH, (p ? Fl : Fh) + kc * 64, tid);
    }
    __syncthreads();

    for (int ch = 0; ch < 2; ch++) {
        float acc[2][8][4];
#pragma unroll
        for (int a = 0; a < 2; a++)
#pragma unroll
            for (int g = 0; g < 8; g++)
#pragma unroll
                for (int q = 0; q < 4; q++) acc[a][g][q] = 0.f;

#pragma unroll 1
        for (int kc = 0; kc < 4; kc++) {
            const int t = ch * 4 + kc;
            CPA_WAIT0();
            __syncthreads();
            if (t + 1 < 8) {
                int ch2 = (t + 1) >> 2, kc2 = (t + 1) & 3;
                uint32_t d = smb + OFF_B + ((t + 1) & 1) * BUFSZ;
                cpa_chunk(d, g_Gk_hi + (ch2 * 128) * CC + kc2 * 64, tid);
                cpa_chunk(d + CH, g_Gk_lo + (ch2 * 128) * CC + kc2 * 64, tid);
            }
            CPA_COMMIT();
            uint32_t bq = smb + OFF_B + (t & 1) * BUFSZ;
            mma_kchunk(smb + OFF_A + kc * CH, smb + OFF_A + (4 + kc) * CH,
                       bq, bq + CH, aro0, bro, lhi, xorv, acc);
        }

        const int g8 = lane >> 2, tig = lane & 3;
#pragma unroll
        for (int a = 0; a < 2; a++)
#pragma unroll
            for (int h = 0; h < 2; h++) {
                const int r = wr * 32 + a * 16 + h * 8 + g8;
                size_t rowoff = ((size_t)b * NN + m0 + r) * CC + ch * 128;
#pragma unroll
                for (int g = 0; g < 8; g++) {
                    const int cl = wc * 64 + g * 8 + tig * 2;
                    float x0 = acc[a][g][h * 2], x1 = acc[a][g][h * 2 + 1];
                    __nv_bfloat16 h0 = __float2bfloat16(x0), h1 = __float2bfloat16(x1);
                    __nv_bfloat16 l0 = __float2bfloat16(x0 - __bfloat162float(h0));
                    __nv_bfloat16 l1 = __float2bfloat16(x1 - __bfloat162float(h1));
                    *(__nv_bfloat162*)(g_Zt_hi + rowoff + cl) = __nv_bfloat162(h0, h1);
                    *(__nv_bfloat162*)(g_Zt_lo + rowoff + cl) = __nv_bfloat162(l0, l1);
                }
            }
    }
}

// ---------------------------------------------------------------------------
// k_attn_mma: streaming S = Ft·Zt^T. 512 threads, 8x2 warp layout (16 rows x
// 64 cols per warp) -> 32-reg accumulators, 4 warps/SMSP for latency hiding.
// Warp-private partial softmax per 64-col slice; two-partial merge at end.
// grid (32, 8), 512 thr.
// ---------------------------------------------------------------------------
__global__ void __launch_bounds__(512, 1) k_attn_mma(const float* __restrict__ feat,
                                                     float* __restrict__ out) {
    extern __shared__ char sm[];
    const uint32_t smb = smem_u32(sm);
    const int tid = threadIdx.x, wid = tid >> 5, lane = tid & 31;
    const int n0 = blockIdx.x * 128, b = blockIdx.y;
    const int wr = wid & 7, wc = wid >> 3;
    const int l15 = lane & 15, g8 = lane >> 2, tig = lane & 3;
    const uint32_t lhi = (uint32_t)((lane >> 4) * 16);
    const uint32_t xorv = (uint32_t)((lane & 7) * 16);
    const uint32_t aro0 = (uint32_t)((wr * 16 + l15) * 128);
    uint32_t bro[4];
#pragma unroll
    for (int g16 = 0; g16 < 4; g16++) bro[g16] = (uint32_t)((wc * 64 + g16 * 16 + l15) * 128);

    float* dlog = (float*)(sm + EP_DLOG);
    float* mmH  = (float*)(sm + EP_MM);    // [2][128]
    float* llH  = (float*)(sm + EP_LL);    // [2][128]
    float* diag = (float*)(sm + EP_DIAG);

    const __nv_bfloat16* Zh = g_Zt_hi + (size_t)b * NN * CC;
    const __nv_bfloat16* Zl = g_Zt_lo + (size_t)b * NN * CC;

    cpa_chunk512(smb + OFF_B, Zh, tid);
    cpa_chunk512(smb + OFF_B + CH, Zl, tid);
    CPA_COMMIT();

    const __nv_bfloat16* Fh = g_Ft_hi + ((size_t)b * NN + n0) * CC;
    const __nv_bfloat16* Fl = g_Ft_lo + ((size_t)b * NN + n0) * CC;
#pragma unroll
    for (int cb = 0; cb < 8; cb++) {
        int p = cb >> 2, kc = cb & 3;
        copy_chunk512(sm, OFF_A + cb * CH, (p ? Fl : Fh) + kc * 64, tid);
    }
    __syncthreads();

    // warp-private online softmax state: 2 rows per lane
    // h=0 -> row wr*16 + g8;  h=1 -> row wr*16 + 8 + g8
    float runm[2] = {-CUDART_INF_F, -CUDART_INF_F};
    float runl[2] = {0.f, 0.f};

#pragma unroll 1
    for (int mt = 0; mt < 32; mt++) {
        float acc[8][4];
#pragma unroll
        for (int g = 0; g < 8; g++)
#pragma unroll
            for (int q = 0; q < 4; q++) acc[g][q] = 0.f;

#pragma unroll 1
        for (int kc = 0; kc < 4; kc++) {
            const int t = mt * 4 + kc;
            CPA_WAIT0();
            __syncthreads();
            if (t + 1 < 128) {
                int mt2 = (t + 1) >> 2, kc2 = (t + 1) & 3;
                uint32_t d = smb + OFF_B + ((t + 1) & 1) * BUFSZ;
                cpa_chunk512(d, Zh + (size_t)(mt2 * 128) * CC + kc2 * 64, tid);
                cpa_chunk512(d + CH, Zl + (size_t)(mt2 * 128) * CC + kc2 * 64, tid);
            }
            CPA_COMMIT();
            uint32_t bq = smb + OFF_B + (t & 1) * BUFSZ;
            mma_kchunk_82(smb + OFF_A + kc * CH, smb + OFF_A + (4 + kc) * CH,
                          bq, bq + CH, aro0, bro, lhi, xorv, acc);
        }

        // ---- warp-private partial softmax over the 64-col slice (no barriers) ----
#pragma unroll
        for (int h = 0; h < 2; h++) {
            float mx = -CUDART_INF_F;
#pragma unroll
            for (int g = 0; g < 8; g++)
                mx = fmaxf(mx, fmaxf(acc[g][h * 2], acc[g][h * 2 + 1]));
            mx = fmaxf(mx, __shfl_xor_sync(0xffffffffu, mx, 1));
            mx = fmaxf(mx, __shfl_xor_sync(0xffffffffu, mx, 2));
            const float nm = fmaxf(runm[h], mx);
            float s = 0.f;
#pragma unroll
            for (int g = 0; g < 8; g++) {
                s += __expf(acc[g][h * 2] - nm);
                s += __expf(acc[g][h * 2 + 1] - nm);
            }
            s += __shfl_xor_sync(0xffffffffu, s, 1);
            s += __shfl_xor_sync(0xffffffffu, s, 2);
            runl[h] = runl[h] * __expf(runm[h] - nm) + s;
            runm[h] = nm;
        }

        if (mt == blockIdx.x) {  // diagonal tile: capture raw logit l_nn
#pragma unroll
            for (int h = 0; h < 2; h++) {
                const int rl = wr * 16 + h * 8 + g8;
#pragma unroll
                for (int g = 0; g < 8; g++)
#pragma unroll
                    for (int j = 0; j < 2; j++) {
                        const int cl = wc * 64 + g * 8 + tig * 2 + j;
                        if (cl == rl) dlog[rl] = acc[g][h * 2 + j];
                    }
            }
        }
    }

    // ---- one-time merge of the two half-row partials ----
    if (tig == 0) {
#pragma unroll
        for (int h = 0; h < 2; h++) {
            const int rl = wr * 16 + h * 8 + g8;
            mmH[wc * 128 + rl] = runm[h];
            llH[wc * 128 + rl] = runl[h];
        }
    }
    __syncthreads();
    if (tid < 128) {
        float m0 = mmH[tid], m1 = mmH[128 + tid];
        float m = fmaxf(m0, m1);
        float l = llH[tid] * __expf(m0 - m) + llH[128 + tid] * __expf(m1 - m);
        diag[tid] = __expf(dlog[tid] - m) / l;
    }
    __syncthreads();

    const float* F = feat + (size_t)b * CC * NN;
    float* O = out + (size_t)b * CC * NN;
    for (int u = tid; u < CC * 32; u += 512) {
        int c = u >> 5, seg = u & 31;
        float4 f = *(const float4*)(F + (size_t)c * NN + n0 + seg * 4);
        float4 o;
        o.x = f.x * diag[seg * 4 + 0];
        o.y = f.y * diag[seg * 4 + 1];
        o.z = f.z * diag[seg * 4 + 2];
        o.w = f.w * diag[seg * 4 + 3];
        *(float4*)(O + (size_t)c * NN + n0 + seg * 4) = o;
    }
}

// ---------------------------------------------------------------------------
extern "C" void kernel_launch(void* const* d_in, const int* in_sizes, int n_in,
                              void* d_out, int out_size) {
    const float* feat = (const float*)d_in[0];  // [B,C,N]
    const float* Wq   = (const float*)d_in[1];  // [C,C]
    const float* Wk   = (const float*)d_in[2];  // [C,C]
    float* out = (float*)d_out;                 // [B,C,N]

    cudaFuncSetAttribute(k_z_mma, cudaFuncAttributeMaxDynamicSharedMemorySize, SMEM_TOTAL);
    cudaFuncSetAttribute(k_attn_mma, cudaFuncAttributeMaxDynamicSharedMemorySize, SMEM_TOTAL);

    k_gt<<<CC / 2, CC>>>(Wq, Wk);
    k_prep<<<dim3(NN / 32, CC / 32, BB), dim3(32, 8)>>>(feat);
    k_z_mma<<<dim3(NN / 128, BB), 256, SMEM_TOTAL>>>();
    k_attn_mma<<<dim3(NN / 128, BB), 512, SMEM_TOTAL>>>(feat, out);
}